// round 1
// baseline (speedup 1.0000x reference)
#include <cuda_runtime.h>
#include <math.h>

// Shapes (fixed per reference): U=256, D=5120, N=16, R=160
#define U_DIM 256
#define D_DIM 5120
#define N_DIM 16
#define R_DIM 160

// ---------------- Stage 1: split-K GEMM  t_ext[U,176] = x[U,5120] @ [W1 | Bp] ----
// cols 0..159 -> t = x@W1, cols 160..175 -> B = x@B_proj_w
#define S1_UT   64     // u per block
#define S1_KC   128    // K per split
#define S1_KK   32     // K per shared iteration
#define S1_NS   40     // number of K splits (5120/128)
#define NCOL    176

__device__ float g_partial[S1_NS * U_DIM * NCOL];   // 7.2 MB scratch
__device__ float g_tbuf[U_DIM * NCOL];

__global__ void __launch_bounds__(256) stage1_kernel(
    const float* __restrict__ x,
    const float* __restrict__ W1,   // [5120,160]
    const float* __restrict__ Bp)   // [5120,16]
{
    __shared__ float x_sh[S1_UT][S1_KK];
    __shared__ float w_sh[S1_KK][NCOL];

    const int bx = blockIdx.x;          // u tile 0..3
    const int by = blockIdx.y;          // k split 0..39
    const int tid = threadIdx.x;
    const int cx = tid & 31;            // column lane
    const int uy = tid >> 5;            // 0..7

    float acc[8][6];
#pragma unroll
    for (int uu = 0; uu < 8; ++uu)
#pragma unroll
        for (int cc = 0; cc < 6; ++cc) acc[uu][cc] = 0.f;

    const int k0 = by * S1_KC;

    for (int it = 0; it < S1_KC / S1_KK; ++it) {
        const int kb = k0 + it * S1_KK;
        // load x tile 64x32
        for (int e = tid; e < S1_UT * S1_KK; e += 256) {
            int u = e >> 5, k = e & 31;
            x_sh[u][k] = x[(size_t)(bx * S1_UT + u) * D_DIM + kb + k];
        }
        // load W1 rows 32x160
        for (int e = tid; e < S1_KK * R_DIM; e += 256) {
            int k = e / R_DIM, r = e % R_DIM;
            w_sh[k][r] = W1[(size_t)(kb + k) * R_DIM + r];
        }
        // load Bp rows 32x16 into cols 160..175
        for (int e = tid; e < S1_KK * N_DIM; e += 256) {
            int k = e >> 4, n = e & 15;
            w_sh[k][R_DIM + n] = Bp[(size_t)(kb + k) * N_DIM + n];
        }
        __syncthreads();

#pragma unroll 8
        for (int kk = 0; kk < S1_KK; ++kk) {
            float xv[8];
#pragma unroll
            for (int uu = 0; uu < 8; ++uu) xv[uu] = x_sh[uu * 8 + uy][kk];
#pragma unroll
            for (int cc = 0; cc < 5; ++cc) {
                float wv = w_sh[kk][cx + 32 * cc];
#pragma unroll
                for (int uu = 0; uu < 8; ++uu) acc[uu][cc] = fmaf(xv[uu], wv, acc[uu][cc]);
            }
            if (cx < 16) {
                float wv = w_sh[kk][R_DIM + cx];
#pragma unroll
                for (int uu = 0; uu < 8; ++uu) acc[uu][5] = fmaf(xv[uu], wv, acc[uu][5]);
            }
        }
        __syncthreads();
    }

    float* pout = g_partial + (size_t)by * (U_DIM * NCOL);
#pragma unroll
    for (int uu = 0; uu < 8; ++uu) {
        const int ug = bx * S1_UT + uu * 8 + uy;
#pragma unroll
        for (int cc = 0; cc < 5; ++cc)
            pout[(size_t)ug * NCOL + cx + 32 * cc] = acc[uu][cc];
        if (cx < 16)
            pout[(size_t)ug * NCOL + R_DIM + cx] = acc[uu][5];
    }
}

// ---------------- Stage 2: reduce 40 split partials -----------------------------
__global__ void __launch_bounds__(256) reduce_kernel() {
    const int idx = blockIdx.x * 256 + threadIdx.x;
    if (idx < U_DIM * NCOL) {
        float s = 0.f;
#pragma unroll
        for (int sp = 0; sp < S1_NS; ++sp)
            s += g_partial[(size_t)sp * (U_DIM * NCOL) + idx];
        g_tbuf[idx] = s;
    }
}

// ---------------- Stage 3: fused dt-GEMM (K=160) + softplus + elementwise -------
#define C_UT 32   // u per block
#define C_DT 128  // d per block
// dyn smem floats: t_sh 32*160 + w_sh 160*128 + b_sh 32*16 + bias_sh 128 = 26240
#define C_SMEM_FLOATS (C_UT * R_DIM + R_DIM * C_DT + C_UT * N_DIM + C_DT)
#define C_SMEM_BYTES  (C_SMEM_FLOATS * 4)

__global__ void __launch_bounds__(256) fused_kernel(
    const float* __restrict__ W2,    // [160,5120]
    const float* __restrict__ bias,  // [5120]
    const float* __restrict__ x,     // [256,5120]
    const float* __restrict__ abar,  // [256,5120,16]
    const float* __restrict__ hst,   // [256,5120,16]
    float* __restrict__ out)
{
    extern __shared__ float sm[];
    float* t_sh    = sm;                          // [32][160]
    float* w_sh    = t_sh + C_UT * R_DIM;         // [160][128]
    float* b_sh    = w_sh + R_DIM * C_DT;         // [32][16]
    float* bias_sh = b_sh + C_UT * N_DIM;         // [128]

    const int u0 = blockIdx.x * C_UT;
    const int d0 = blockIdx.y * C_DT;
    const int tid = threadIdx.x;

    // stage t tile
    for (int e = tid; e < C_UT * R_DIM; e += 256) {
        int u = e / R_DIM, r = e % R_DIM;
        t_sh[u * R_DIM + r] = g_tbuf[(size_t)(u0 + u) * NCOL + r];
    }
    // stage W2 tile [160][128]
    for (int e = tid; e < R_DIM * C_DT; e += 256) {
        int r = e >> 7, d = e & 127;
        w_sh[r * C_DT + d] = W2[(size_t)r * D_DIM + d0 + d];
    }
    // stage B tile [32][16]
    for (int e = tid; e < C_UT * N_DIM; e += 256) {
        int u = e >> 4, n = e & 15;
        b_sh[e] = g_tbuf[(size_t)(u0 + u) * NCOL + R_DIM + n];
    }
    if (tid < C_DT) bias_sh[tid] = bias[d0 + tid];
    __syncthreads();

    const int td = tid & 31;   // d lane
    const int tu = tid >> 5;   // 0..7 (u group)

    float acc[4][4];
#pragma unroll
    for (int uu = 0; uu < 4; ++uu)
#pragma unroll
        for (int dd = 0; dd < 4; ++dd) acc[uu][dd] = 0.f;

#pragma unroll 4
    for (int r = 0; r < R_DIM; ++r) {
        float wv[4];
#pragma unroll
        for (int dd = 0; dd < 4; ++dd) wv[dd] = w_sh[r * C_DT + td + 32 * dd];
#pragma unroll
        for (int uu = 0; uu < 4; ++uu) {
            float tv = t_sh[(tu * 4 + uu) * R_DIM + r];
#pragma unroll
            for (int dd = 0; dd < 4; ++dd) acc[uu][dd] = fmaf(tv, wv[dd], acc[uu][dd]);
        }
    }

    // epilogue: softplus, then stream abar/h/out
#pragma unroll
    for (int uu = 0; uu < 4; ++uu) {
        const int ul = tu * 4 + uu;
        const int u  = u0 + ul;
        const float4* B4 = (const float4*)(b_sh + ul * N_DIM);
        float4 bb0 = B4[0], bb1 = B4[1], bb2 = B4[2], bb3 = B4[3];
#pragma unroll
        for (int dd = 0; dd < 4; ++dd) {
            const int d = d0 + td + 32 * dd;
            const float z = acc[uu][dd] + bias_sh[td + 32 * dd];
            const float dt = fmaxf(z, 0.f) + log1pf(expf(-fabsf(z)));
            const float c1 = dt * x[(size_t)u * D_DIM + d];
            const size_t base = ((size_t)u * D_DIM + d) * N_DIM;
            const float4* a4 = (const float4*)(abar + base);
            const float4* h4 = (const float4*)(hst + base);
            float4*       o4 = (float4*)(out + base);

            float4 a, hh, o;
            a = a4[0]; hh = h4[0];
            o.x = fmaf(a.x, hh.x, c1 * bb0.x); o.y = fmaf(a.y, hh.y, c1 * bb0.y);
            o.z = fmaf(a.z, hh.z, c1 * bb0.z); o.w = fmaf(a.w, hh.w, c1 * bb0.w);
            o4[0] = o;
            a = a4[1]; hh = h4[1];
            o.x = fmaf(a.x, hh.x, c1 * bb1.x); o.y = fmaf(a.y, hh.y, c1 * bb1.y);
            o.z = fmaf(a.z, hh.z, c1 * bb1.z); o.w = fmaf(a.w, hh.w, c1 * bb1.w);
            o4[1] = o;
            a = a4[2]; hh = h4[2];
            o.x = fmaf(a.x, hh.x, c1 * bb2.x); o.y = fmaf(a.y, hh.y, c1 * bb2.y);
            o.z = fmaf(a.z, hh.z, c1 * bb2.z); o.w = fmaf(a.w, hh.w, c1 * bb2.w);
            o4[2] = o;
            a = a4[3]; hh = h4[3];
            o.x = fmaf(a.x, hh.x, c1 * bb3.x); o.y = fmaf(a.y, hh.y, c1 * bb3.y);
            o.z = fmaf(a.z, hh.z, c1 * bb3.z); o.w = fmaf(a.w, hh.w, c1 * bb3.w);
            o4[3] = o;
        }
    }
}

extern "C" void kernel_launch(void* const* d_in, const int* in_sizes, int n_in,
                              void* d_out, int out_size) {
    const float* x    = (const float*)d_in[0];   // [256,5120]
    const float* W1   = (const float*)d_in[1];   // [5120,160]
    const float* W2   = (const float*)d_in[2];   // [160,5120]
    const float* bias = (const float*)d_in[3];   // [5120]
    const float* Bp   = (const float*)d_in[4];   // [5120,16]
    const float* abar = (const float*)d_in[5];   // [256,5120,16]
    const float* hst  = (const float*)d_in[6];   // [256,5120,16]
    float* out = (float*)d_out;

    stage1_kernel<<<dim3(U_DIM / S1_UT, S1_NS), 256>>>(x, W1, Bp);
    reduce_kernel<<<(U_DIM * NCOL + 255) / 256, 256>>>();

    cudaFuncSetAttribute(fused_kernel,
                         cudaFuncAttributeMaxDynamicSharedMemorySize, C_SMEM_BYTES);
    fused_kernel<<<dim3(U_DIM / C_UT, D_DIM / C_DT), 256, C_SMEM_BYTES>>>(
        W2, bias, x, abar, hst, out);
}

// round 2
// speedup vs baseline: 1.4066x; 1.4066x over previous
#include <cuda_runtime.h>
#include <math.h>

// Shapes (fixed per reference): U=256, D=5120, N=16, R=160
#define U_DIM 256
#define D_DIM 5120
#define N_DIM 16
#define R_DIM 160
#define NCOL  176   // 160 (t) + 16 (B)

// ---------------- scratch ----------------
#define S1_SPLITS 80
#define S1_KC     64     // K per split
#define S1_UT     32     // u per block
#define S1_KK     32     // K per smem stage

__device__ float g_partial[S1_SPLITS * U_DIM * NCOL];   // 14.4 MB
__device__ float g_tbuf[U_DIM * NCOL];                  // t | B
__device__ float g_dt[U_DIM * D_DIM];                   // 5 MB dt

// ================= Stage 1: split-K GEMM  t_ext[U,176] = x @ [W1 | Bp] ==========
__global__ void __launch_bounds__(256) stage1_kernel(
    const float* __restrict__ x,
    const float* __restrict__ W1,   // [5120,160]
    const float* __restrict__ Bp)   // [5120,16]
{
    __shared__ float x_sh[S1_UT][S1_KK];
    __shared__ float w_sh[S1_KK][NCOL];

    const int bx  = blockIdx.x;     // u tile 0..7
    const int by  = blockIdx.y;     // k split 0..79
    const int tid = threadIdx.x;
    const int cx  = tid & 31;       // column lane
    const int uy  = tid >> 5;       // warp id 0..7

    float acc[4][6];
#pragma unroll
    for (int uu = 0; uu < 4; ++uu)
#pragma unroll
        for (int cc = 0; cc < 6; ++cc) acc[uu][cc] = 0.f;

    const int k0 = by * S1_KC;

#pragma unroll
    for (int it = 0; it < S1_KC / S1_KK; ++it) {
        const int kb = k0 + it * S1_KK;
        // x tile 32x32
        for (int e = tid; e < S1_UT * S1_KK; e += 256) {
            int u = e >> 5, k = e & 31;
            x_sh[u][k] = x[(size_t)(bx * S1_UT + u) * D_DIM + kb + k];
        }
        // W1 rows 32x160
        for (int e = tid; e < S1_KK * R_DIM; e += 256) {
            int k = e / R_DIM, r = e % R_DIM;
            w_sh[k][r] = W1[(size_t)(kb + k) * R_DIM + r];
        }
        // Bp rows 32x16 -> cols 160..175
        for (int e = tid; e < S1_KK * N_DIM; e += 256) {
            int k = e >> 4, n = e & 15;
            w_sh[k][R_DIM + n] = Bp[(size_t)(kb + k) * N_DIM + n];
        }
        __syncthreads();

#pragma unroll 8
        for (int kk = 0; kk < S1_KK; ++kk) {
            float xv[4];
#pragma unroll
            for (int uu = 0; uu < 4; ++uu) xv[uu] = x_sh[uu * 8 + uy][kk];
#pragma unroll
            for (int cc = 0; cc < 5; ++cc) {
                float wv = w_sh[kk][cx + 32 * cc];
#pragma unroll
                for (int uu = 0; uu < 4; ++uu) acc[uu][cc] = fmaf(xv[uu], wv, acc[uu][cc]);
            }
            if (cx < 16) {
                float wv = w_sh[kk][R_DIM + cx];
#pragma unroll
                for (int uu = 0; uu < 4; ++uu) acc[uu][5] = fmaf(xv[uu], wv, acc[uu][5]);
            }
        }
        __syncthreads();
    }

    float* pout = g_partial + (size_t)by * (U_DIM * NCOL);
#pragma unroll
    for (int uu = 0; uu < 4; ++uu) {
        const int ug = bx * S1_UT + uu * 8 + uy;
#pragma unroll
        for (int cc = 0; cc < 5; ++cc)
            pout[(size_t)ug * NCOL + cx + 32 * cc] = acc[uu][cc];
        if (cx < 16)
            pout[(size_t)ug * NCOL + R_DIM + cx] = acc[uu][5];
    }
}

// ================= Stage 2: reduce 80 split partials ============================
__global__ void __launch_bounds__(256) reduce_kernel() {
    const int idx = blockIdx.x * 256 + threadIdx.x;
    if (idx < U_DIM * NCOL) {
        float s = 0.f;
#pragma unroll 16
        for (int sp = 0; sp < S1_SPLITS; ++sp)
            s += g_partial[(size_t)sp * (U_DIM * NCOL) + idx];
        g_tbuf[idx] = s;
    }
}

// ================= Stage 3: dt = softplus(t @ W2 + bias)  -> g_dt ===============
#define DT_UT   32    // u per block
#define DT_DT   128   // d per block (== threads)
#define DT_PITCH 36   // padded pitch for t_sh (float4-aligned, conflict-lite)

__global__ void __launch_bounds__(128) dt_kernel(
    const float* __restrict__ W2,    // [160,5120]
    const float* __restrict__ bias)  // [5120]
{
    __shared__ float t_sh[R_DIM * DT_PITCH];   // [r][u] transposed, 23 KB

    const int u0  = blockIdx.y * DT_UT;
    const int d   = blockIdx.x * DT_DT + threadIdx.x;
    const int tid = threadIdx.x;

    // stage t transposed: t_sh[r*36 + u] = t[u0+u][r]
    for (int e = tid; e < DT_UT * R_DIM; e += 128) {
        int u = e / R_DIM, r = e % R_DIM;
        t_sh[r * DT_PITCH + u] = g_tbuf[(size_t)(u0 + u) * NCOL + r];
    }
    __syncthreads();

    float acc[DT_UT];
#pragma unroll
    for (int u = 0; u < DT_UT; ++u) acc[u] = 0.f;

#pragma unroll 4
    for (int r = 0; r < R_DIM; ++r) {
        const float w = W2[(size_t)r * D_DIM + d];
        const float4* trow = (const float4*)(t_sh + r * DT_PITCH);
#pragma unroll
        for (int q = 0; q < DT_UT / 4; ++q) {
            float4 t4 = trow[q];
            acc[q * 4 + 0] = fmaf(t4.x, w, acc[q * 4 + 0]);
            acc[q * 4 + 1] = fmaf(t4.y, w, acc[q * 4 + 1]);
            acc[q * 4 + 2] = fmaf(t4.z, w, acc[q * 4 + 2]);
            acc[q * 4 + 3] = fmaf(t4.w, w, acc[q * 4 + 3]);
        }
    }

    const float bz = bias[d];
#pragma unroll
    for (int u = 0; u < DT_UT; ++u) {
        const float z  = acc[u] + bz;
        const float dt = fmaxf(z, 0.f) + log1pf(expf(-fabsf(z)));
        g_dt[(size_t)(u0 + u) * D_DIM + d] = dt;
    }
}

// ================= Stage 4: pure streaming elementwise ==========================
// out[u,d,n] = abar*h + (dt[u,d]*x[u,d]) * B[u,n]
#define DBLK 256
__global__ void __launch_bounds__(256) stream_kernel(
    const float* __restrict__ x,
    const float* __restrict__ abar,
    const float* __restrict__ hst,
    float* __restrict__ out)
{
    __shared__ float Bsh[N_DIM];

    const int bid = blockIdx.x;
    const int u   = bid / (D_DIM / DBLK);
    const int d   = (bid % (D_DIM / DBLK)) * DBLK + threadIdx.x;

    if (threadIdx.x < N_DIM)
        Bsh[threadIdx.x] = g_tbuf[(size_t)u * NCOL + R_DIM + threadIdx.x];
    __syncthreads();

    const size_t ud = (size_t)u * D_DIM + d;
    const float c1  = g_dt[ud] * x[ud];

    float4 cb[4];
    const float4* B4 = (const float4*)Bsh;
#pragma unroll
    for (int j = 0; j < 4; ++j) {
        float4 b = B4[j];
        cb[j] = make_float4(c1 * b.x, c1 * b.y, c1 * b.z, c1 * b.w);
    }

    const size_t base = ud * N_DIM;
    const float4* a4 = (const float4*)(abar + base);
    const float4* h4 = (const float4*)(hst  + base);
    float4*       o4 = (float4*)(out + base);

    float4 a[4], h[4];
#pragma unroll
    for (int j = 0; j < 4; ++j) { a[j] = a4[j]; h[j] = h4[j]; }
#pragma unroll
    for (int j = 0; j < 4; ++j) {
        float4 o;
        o.x = fmaf(a[j].x, h[j].x, cb[j].x);
        o.y = fmaf(a[j].y, h[j].y, cb[j].y);
        o.z = fmaf(a[j].z, h[j].z, cb[j].z);
        o.w = fmaf(a[j].w, h[j].w, cb[j].w);
        o4[j] = o;
    }
}

extern "C" void kernel_launch(void* const* d_in, const int* in_sizes, int n_in,
                              void* d_out, int out_size) {
    const float* x    = (const float*)d_in[0];   // [256,5120]
    const float* W1   = (const float*)d_in[1];   // [5120,160]
    const float* W2   = (const float*)d_in[2];   // [160,5120]
    const float* bias = (const float*)d_in[3];   // [5120]
    const float* Bp   = (const float*)d_in[4];   // [5120,16]
    const float* abar = (const float*)d_in[5];   // [256,5120,16]
    const float* hst  = (const float*)d_in[6];   // [256,5120,16]
    float* out = (float*)d_out;

    stage1_kernel<<<dim3(U_DIM / S1_UT, S1_SPLITS), 256>>>(x, W1, Bp);
    reduce_kernel<<<(U_DIM * NCOL + 255) / 256, 256>>>();
    dt_kernel<<<dim3(D_DIM / DT_DT, U_DIM / DT_UT), 128>>>(W2, bias);
    stream_kernel<<<U_DIM * (D_DIM / DBLK), 256>>>(x, abar, hst, out);
}

// round 3
// speedup vs baseline: 1.7083x; 1.2146x over previous
#include <cuda_runtime.h>
#include <math.h>
#include <stdint.h>

// Shapes (fixed): U=256, D=5120, N=16, R=160
#define U_DIM 256
#define D_DIM 5120
#define N_DIM 16
#define R_DIM 160
#define NCOL  176   // 160 (t) + 16 (B)

// ---------------- scratch ----------------
#define S1_SPLITS 80
#define S1_KC     64      // K per split
#define S1_KK     32      // K per smem stage
#define S1_UT     64      // u per block
#define XPITCH    68      // xT smem pitch (16B-aligned rows)
#define WPITCH    176

__device__ float g_partial[S1_SPLITS * U_DIM * NCOL];   // 14.4 MB
__device__ float g_tbuf[U_DIM * NCOL];                  // t | B
__device__ float g_c1[U_DIM * D_DIM];                   // c1 = dt * x

// ---------------- f32x2 helpers ----------------
__device__ __forceinline__ unsigned long long pack2(float v) {
    unsigned long long r;
    asm("mov.b64 %0, {%1, %1};" : "=l"(r) : "f"(v));
    return r;
}
__device__ __forceinline__ void fma2(unsigned long long& acc,
                                     unsigned long long a, unsigned long long b) {
    asm("fma.rn.f32x2 %0, %1, %2, %0;" : "+l"(acc) : "l"(a), "l"(b));
}
__device__ __forceinline__ void lds_v2b64(unsigned long long& a, unsigned long long& b,
                                          uint32_t addr) {
    asm volatile("ld.shared.v2.b64 {%0, %1}, [%2];" : "=l"(a), "=l"(b) : "r"(addr));
}
__device__ __forceinline__ void unpack2(unsigned long long p, float& lo, float& hi) {
    asm("mov.b64 {%0, %1}, %2;" : "=f"(lo), "=f"(hi) : "l"(p));
}

// ================= Stage 1: split-K GEMM  t_ext[U,176] = x @ [W1 | Bp] ==========
// grid (4 u-tiles, 80 k-splits), block 256. Warp w owns u rows w*8..w*8+7 (4 pairs),
// lane cx owns cols {cx, cx+32, ..., cx+128} + (cx<16 ? 160+cx : -)
__global__ void __launch_bounds__(256) stage1_kernel(
    const float* __restrict__ x,
    const float* __restrict__ W1,   // [5120,160]
    const float* __restrict__ Bp)   // [5120,16]
{
    __shared__ __align__(16) float xT[S1_KK * XPITCH];        // [k][u] transposed
    __shared__ __align__(16) float wsh[S1_KK * WPITCH + 32];  // [k][col], padded

    const int bx  = blockIdx.x;
    const int by  = blockIdx.y;
    const int tid = threadIdx.x;
    const int cx  = tid & 31;
    const int wid = tid >> 5;

    unsigned long long acc[4][6];
#pragma unroll
    for (int up = 0; up < 4; ++up)
#pragma unroll
        for (int c = 0; c < 6; ++c) acc[up][c] = 0ULL;

    const int k0 = by * S1_KC;
    const int u0 = bx * S1_UT;
    const uint32_t xT_base = (uint32_t)__cvta_generic_to_shared(xT);

#pragma unroll
    for (int st = 0; st < S1_KC / S1_KK; ++st) {
        const int kb = k0 + st * S1_KK;
        // stage x transposed: xT[k][u]
        for (int e = tid; e < S1_UT * S1_KK; e += 256) {
            int u = e >> 5, k = e & 31;
            xT[k * XPITCH + u] = x[(size_t)(u0 + u) * D_DIM + kb + k];
        }
        // stage W1 rows
        for (int e = tid; e < S1_KK * R_DIM; e += 256) {
            int k = e / R_DIM, r = e - k * R_DIM;
            wsh[k * WPITCH + r] = W1[(size_t)(kb + k) * R_DIM + r];
        }
        // stage Bp rows -> cols 160..175
        for (int e = tid; e < S1_KK * N_DIM; e += 256) {
            int k = e >> 4, n = e & 15;
            wsh[k * WPITCH + R_DIM + n] = Bp[(size_t)(kb + k) * N_DIM + n];
        }
        __syncthreads();

#pragma unroll 4
        for (int kk = 0; kk < S1_KK; ++kk) {
            unsigned long long xp[4];
            const uint32_t a0 = xT_base + (uint32_t)(kk * XPITCH + wid * 8) * 4u;
            lds_v2b64(xp[0], xp[1], a0);
            lds_v2b64(xp[2], xp[3], a0 + 16u);
            const float* wrow = wsh + kk * WPITCH;
#pragma unroll
            for (int c = 0; c < 5; ++c) {
                unsigned long long wp = pack2(wrow[cx + 32 * c]);
#pragma unroll
                for (int up = 0; up < 4; ++up) fma2(acc[up][c], xp[up], wp);
            }
            {
                float wv = (cx < 16) ? wrow[R_DIM + cx] : 0.f;
                unsigned long long wp = pack2(wv);
#pragma unroll
                for (int up = 0; up < 4; ++up) fma2(acc[up][5], xp[up], wp);
            }
        }
        __syncthreads();
    }

    float* pout = g_partial + (size_t)by * (U_DIM * NCOL);
#pragma unroll
    for (int up = 0; up < 4; ++up) {
        const int ug = u0 + wid * 8 + up * 2;   // users ug, ug+1
#pragma unroll
        for (int c = 0; c < 5; ++c) {
            float lo, hi; unpack2(acc[up][c], lo, hi);
            pout[(size_t)ug * NCOL + cx + 32 * c]       = lo;
            pout[(size_t)(ug + 1) * NCOL + cx + 32 * c] = hi;
        }
        if (cx < 16) {
            float lo, hi; unpack2(acc[up][5], lo, hi);
            pout[(size_t)ug * NCOL + R_DIM + cx]       = lo;
            pout[(size_t)(ug + 1) * NCOL + R_DIM + cx] = hi;
        }
    }
}

// ================= Stage 2: reduce 80 split partials ============================
__global__ void __launch_bounds__(128) reduce_kernel() {
    const int idx = blockIdx.x * 128 + threadIdx.x;   // grid*block == 45056 exactly
    float s = 0.f;
#pragma unroll 10
    for (int sp = 0; sp < S1_SPLITS; ++sp)
        s += g_partial[(size_t)sp * (U_DIM * NCOL) + idx];
    g_tbuf[idx] = s;
}

// ================= Stage 3: c1 = softplus(t @ W2 + bias) * x  -> g_c1 ===========
#define DT_UT 32
#define DT_DT 128
#define TPITCH 36   // 144B rows, 16B-aligned

__global__ void __launch_bounds__(128) dt_kernel(
    const float* __restrict__ W2,    // [160,5120]
    const float* __restrict__ bias,  // [5120]
    const float* __restrict__ x)     // [256,5120]
{
    __shared__ __align__(16) float tsh[R_DIM * TPITCH];  // [r][u] transposed, 23KB

    const int u0 = blockIdx.y * DT_UT;
    const int d  = blockIdx.x * DT_DT + threadIdx.x;

    for (int e = threadIdx.x; e < DT_UT * R_DIM; e += 128) {
        int u = e / R_DIM, r = e - u * R_DIM;
        tsh[r * TPITCH + u] = g_tbuf[(size_t)(u0 + u) * NCOL + r];
    }
    __syncthreads();

    unsigned long long acc[16];
#pragma unroll
    for (int i = 0; i < 16; ++i) acc[i] = 0ULL;

    const uint32_t tb = (uint32_t)__cvta_generic_to_shared(tsh);
#pragma unroll 2
    for (int r = 0; r < R_DIM; ++r) {
        const unsigned long long wp = pack2(W2[(size_t)r * D_DIM + d]);
        const uint32_t a = tb + (uint32_t)(r * TPITCH) * 4u;
#pragma unroll
        for (int q = 0; q < 8; ++q) {
            unsigned long long p0, p1;
            lds_v2b64(p0, p1, a + (uint32_t)q * 16u);
            fma2(acc[2 * q],     p0, wp);
            fma2(acc[2 * q + 1], p1, wp);
        }
    }

    const float bz = bias[d];
#pragma unroll
    for (int i = 0; i < 16; ++i) {
        float z0, z1; unpack2(acc[i], z0, z1);
        const int u = u0 + 2 * i;
        z0 += bz; z1 += bz;
        const float dt0 = fmaxf(z0, 0.f) + log1pf(expf(-fabsf(z0)));
        const float dt1 = fmaxf(z1, 0.f) + log1pf(expf(-fabsf(z1)));
        g_c1[(size_t)u * D_DIM + d]       = dt0 * x[(size_t)u * D_DIM + d];
        g_c1[(size_t)(u + 1) * D_DIM + d] = dt1 * x[(size_t)(u + 1) * D_DIM + d];
    }
}

// ================= Stage 4: streaming elementwise (perfectly coalesced) =========
// out4[f] = a4[f]*h4[f] + c1[f>>2] * B4[u][f&3]
#define F4_PER_U (D_DIM * N_DIM / 4)   // 20480
#define F4_PER_BLK 1024                // 20 blocks per u

__global__ void __launch_bounds__(256) stream_kernel(
    const float4* __restrict__ abar4,
    const float4* __restrict__ hst4,
    float4* __restrict__ out4)
{
    const int bid = blockIdx.x;
    const int t   = threadIdx.x;
    const int u   = bid / (F4_PER_U / F4_PER_BLK);
    const size_t wb = (size_t)bid * F4_PER_BLK + (size_t)(t >> 5) * 128 + (t & 31);

    const float4* Bu = (const float4*)(g_tbuf + u * NCOL + R_DIM);
    const float4 b = __ldg(Bu + (t & 3));

#pragma unroll
    for (int j = 0; j < 4; ++j) {
        const size_t f = wb + 32 * j;
        const float c1 = __ldg(g_c1 + (f >> 2));
        const float4 a = __ldcs(abar4 + f);
        const float4 h = __ldcs(hst4 + f);
        float4 o;
        o.x = fmaf(a.x, h.x, c1 * b.x);
        o.y = fmaf(a.y, h.y, c1 * b.y);
        o.z = fmaf(a.z, h.z, c1 * b.z);
        o.w = fmaf(a.w, h.w, c1 * b.w);
        __stcs(out4 + f, o);
    }
}

extern "C" void kernel_launch(void* const* d_in, const int* in_sizes, int n_in,
                              void* d_out, int out_size) {
    const float* x    = (const float*)d_in[0];   // [256,5120]
    const float* W1   = (const float*)d_in[1];   // [5120,160]
    const float* W2   = (const float*)d_in[2];   // [160,5120]
    const float* bias = (const float*)d_in[3];   // [5120]
    const float* Bp   = (const float*)d_in[4];   // [5120,16]
    const float* abar = (const float*)d_in[5];   // [256,5120,16]
    const float* hst  = (const float*)d_in[6];   // [256,5120,16]
    float* out = (float*)d_out;

    stage1_kernel<<<dim3(U_DIM / S1_UT, S1_SPLITS), 256>>>(x, W1, Bp);
    reduce_kernel<<<U_DIM * NCOL / 128, 128>>>();
    dt_kernel<<<dim3(D_DIM / DT_DT, U_DIM / DT_UT), 128>>>(W2, bias, x);
    stream_kernel<<<U_DIM * (F4_PER_U / F4_PER_BLK), 256>>>(
        (const float4*)abar, (const float4*)hst, (float4*)out);
}

// round 4
// speedup vs baseline: 1.8120x; 1.0607x over previous
#include <cuda_runtime.h>
#include <math.h>
#include <stdint.h>

// Shapes (fixed): U=256, D=5120, N=16, R=160
#define U_DIM 256
#define D_DIM 5120
#define N_DIM 16
#define R_DIM 160
#define NCOL  176   // 160 (t) + 16 (B)

// ---------------- scratch ----------------
#define S1_SPLITS 80
#define S1_KC     64      // K per split
#define S1_KK     32      // K per smem stage
#define S1_UT     32      // u per block
#define XPITCH    36      // xT smem pitch
#define WPITCH    176

__device__ float g_partial[S1_SPLITS * U_DIM * NCOL];   // 14.4 MB
__device__ float g_tbuf[U_DIM * NCOL];                  // t | B

// ---------------- f32x2 helpers ----------------
__device__ __forceinline__ unsigned long long pack2(float v) {
    unsigned long long r;
    asm("mov.b64 %0, {%1, %1};" : "=l"(r) : "f"(v));
    return r;
}
__device__ __forceinline__ void fma2(unsigned long long& acc,
                                     unsigned long long a, unsigned long long b) {
    asm("fma.rn.f32x2 %0, %1, %2, %0;" : "+l"(acc) : "l"(a), "l"(b));
}
__device__ __forceinline__ void lds_v2b64(unsigned long long& a, unsigned long long& b,
                                          uint32_t addr) {
    asm volatile("ld.shared.v2.b64 {%0, %1}, [%2];" : "=l"(a), "=l"(b) : "r"(addr));
}
__device__ __forceinline__ void unpack2(unsigned long long p, float& lo, float& hi) {
    asm("mov.b64 {%0, %1}, %2;" : "=f"(lo), "=f"(hi) : "l"(p));
}

// ================= Stage 1: split-K GEMM  t_ext[U,176] = x @ [W1 | Bp] ==========
// grid (8 u-tiles, 80 k-splits), block 256. Warp w owns users w*4..w*4+3 (2 pairs),
// lane cx owns cols {cx, cx+32, ..., cx+128} + (cx<16 ? 160+cx : -)
__global__ void __launch_bounds__(256) stage1_kernel(
    const float* __restrict__ x,
    const float* __restrict__ W1,   // [5120,160]
    const float* __restrict__ Bp)   // [5120,16]
{
    __shared__ __align__(16) float xT[S1_KK * XPITCH];        // [k][u] transposed
    __shared__ __align__(16) float wsh[S1_KK * WPITCH + 32];  // [k][col]

    const int bx  = blockIdx.x;
    const int by  = blockIdx.y;
    const int tid = threadIdx.x;
    const int cx  = tid & 31;
    const int wid = tid >> 5;

    unsigned long long acc[2][6];
#pragma unroll
    for (int up = 0; up < 2; ++up)
#pragma unroll
        for (int c = 0; c < 6; ++c) acc[up][c] = 0ULL;

    const int k0 = by * S1_KC;
    const int u0 = bx * S1_UT;
    const uint32_t xT_base = (uint32_t)__cvta_generic_to_shared(xT);

#pragma unroll
    for (int st = 0; st < S1_KC / S1_KK; ++st) {
        const int kb = k0 + st * S1_KK;
        // stage x transposed: xT[k][u]
        for (int e = tid; e < S1_UT * S1_KK; e += 256) {
            int u = e >> 5, k = e & 31;
            xT[k * XPITCH + u] = x[(size_t)(u0 + u) * D_DIM + kb + k];
        }
        // stage W1 rows
        for (int e = tid; e < S1_KK * R_DIM; e += 256) {
            int k = e / R_DIM, r = e - k * R_DIM;
            wsh[k * WPITCH + r] = W1[(size_t)(kb + k) * R_DIM + r];
        }
        // stage Bp rows -> cols 160..175
        for (int e = tid; e < S1_KK * N_DIM; e += 256) {
            int k = e >> 4, n = e & 15;
            wsh[k * WPITCH + R_DIM + n] = Bp[(size_t)(kb + k) * N_DIM + n];
        }
        __syncthreads();

#pragma unroll 8
        for (int kk = 0; kk < S1_KK; ++kk) {
            unsigned long long xp[2];
            lds_v2b64(xp[0], xp[1],
                      xT_base + (uint32_t)(kk * XPITCH + wid * 4) * 4u);
            const float* wrow = wsh + kk * WPITCH;
#pragma unroll
            for (int c = 0; c < 5; ++c) {
                unsigned long long wp = pack2(wrow[cx + 32 * c]);
                fma2(acc[0][c], xp[0], wp);
                fma2(acc[1][c], xp[1], wp);
            }
            {
                float wv = (cx < 16) ? wrow[R_DIM + cx] : 0.f;
                unsigned long long wp = pack2(wv);
                fma2(acc[0][5], xp[0], wp);
                fma2(acc[1][5], xp[1], wp);
            }
        }
        __syncthreads();
    }

    float* pout = g_partial + (size_t)by * (U_DIM * NCOL);
#pragma unroll
    for (int up = 0; up < 2; ++up) {
        const int ug = u0 + wid * 4 + up * 2;   // users ug, ug+1
#pragma unroll
        for (int c = 0; c < 5; ++c) {
            float lo, hi; unpack2(acc[up][c], lo, hi);
            pout[(size_t)ug * NCOL + cx + 32 * c]       = lo;
            pout[(size_t)(ug + 1) * NCOL + cx + 32 * c] = hi;
        }
        if (cx < 16) {
            float lo, hi; unpack2(acc[up][5], lo, hi);
            pout[(size_t)ug * NCOL + R_DIM + cx]       = lo;
            pout[(size_t)(ug + 1) * NCOL + R_DIM + cx] = hi;
        }
    }
}

// ================= Stage 2: reduce 80 split partials (float4) ===================
#define RED_F4 (U_DIM * NCOL / 4)   // 11264
__global__ void __launch_bounds__(256) reduce_kernel() {
    const int idx = blockIdx.x * 256 + threadIdx.x;   // 44 * 256 == 11264 exactly
    const float4* p4 = (const float4*)g_partial;
    float4 s = make_float4(0.f, 0.f, 0.f, 0.f);
#pragma unroll 8
    for (int sp = 0; sp < S1_SPLITS; ++sp) {
        float4 v = __ldcg(p4 + (size_t)sp * RED_F4 + idx);
        s.x += v.x; s.y += v.y; s.z += v.z; s.w += v.w;
    }
    ((float4*)g_tbuf)[idx] = s;
}

// ================= Stage 3: fused dt-GEMM + softplus + streaming ================
// Block: 16 users x 128 d. GEMM phase: thread owns d = d0 + (tid&127), 8 users.
// Stream phase: per u, block streams 512 consecutive float4 (2 per thread).
#define FU_UT 16
#define FU_DT 128

__global__ void __launch_bounds__(256, 5) fused_kernel(
    const float* __restrict__ W2,    // [160,5120]
    const float* __restrict__ bias,  // [5120]
    const float* __restrict__ x,     // [256,5120]
    const float4* __restrict__ abar4,
    const float4* __restrict__ hst4,
    float4* __restrict__ out4)
{
    __shared__ __align__(16) float tsh[R_DIM * FU_UT];     // [r][u] 10.2 KB
    __shared__ __align__(16) float c1sh[FU_UT * FU_DT];    // 8 KB
    __shared__ __align__(16) float Bsh[FU_UT * N_DIM];     // 1 KB

    const int u0  = blockIdx.x * FU_UT;
    const int d0  = blockIdx.y * FU_DT;
    const int tid = threadIdx.x;

    // stage t transposed: tsh[r*16 + u]
    for (int e = tid; e < FU_UT * R_DIM; e += 256) {
        int u = e / R_DIM, r = e - u * R_DIM;
        tsh[r * FU_UT + u] = g_tbuf[(size_t)(u0 + u) * NCOL + r];
    }
    // stage B: tid covers 16u x 16n exactly
    {
        int u = tid >> 4, n = tid & 15;
        Bsh[tid] = g_tbuf[(size_t)(u0 + u) * NCOL + R_DIM + n];
    }
    __syncthreads();

    // ---- GEMM phase ----
    const int dl = tid & 127;
    const int ug = (tid >> 7) * 8;     // 0 or 8
    const int d  = d0 + dl;

    unsigned long long acc[4];
#pragma unroll
    for (int i = 0; i < 4; ++i) acc[i] = 0ULL;

    const uint32_t tb = (uint32_t)__cvta_generic_to_shared(tsh)
                      + (uint32_t)ug * 4u;
#pragma unroll 4
    for (int r = 0; r < R_DIM; ++r) {
        const unsigned long long wp = pack2(__ldg(W2 + (size_t)r * D_DIM + d));
        unsigned long long p0, p1, p2, p3;
        const uint32_t a = tb + (uint32_t)(r * FU_UT) * 4u;
        lds_v2b64(p0, p1, a);
        lds_v2b64(p2, p3, a + 16u);
        fma2(acc[0], p0, wp);
        fma2(acc[1], p1, wp);
        fma2(acc[2], p2, wp);
        fma2(acc[3], p3, wp);
    }

    const float bz = bias[d];
#pragma unroll
    for (int i = 0; i < 4; ++i) {
        float z0, z1; unpack2(acc[i], z0, z1);
        const int u = ug + 2 * i;
        z0 += bz; z1 += bz;
        const float dt0 = fmaxf(z0, 0.f) + log1pf(expf(-fabsf(z0)));
        const float dt1 = fmaxf(z1, 0.f) + log1pf(expf(-fabsf(z1)));
        c1sh[u * FU_DT + dl]       = dt0 * __ldg(x + (size_t)(u0 + u) * D_DIM + d);
        c1sh[(u + 1) * FU_DT + dl] = dt1 * __ldg(x + (size_t)(u0 + u + 1) * D_DIM + d);
    }
    __syncthreads();

    // ---- streaming phase ----
    const int n4 = tid & 3;
    const int i0 = tid;          // f4 index within the u-region [0,512)
    const int i1 = tid + 256;

#pragma unroll 2
    for (int u = 0; u < FU_UT; ++u) {
        const size_t base = ((size_t)(u0 + u) * D_DIM + d0) * 4;  // float4 units
        const float4 b = *(const float4*)(Bsh + u * N_DIM + n4 * 4);
        const float c0 = c1sh[u * FU_DT + (i0 >> 2)];
        const float c1 = c1sh[u * FU_DT + (i1 >> 2)];

        const float4 a0 = __ldcs(abar4 + base + i0);
        const float4 h0 = __ldcs(hst4  + base + i0);
        const float4 a1 = __ldcs(abar4 + base + i1);
        const float4 h1 = __ldcs(hst4  + base + i1);

        float4 o0, o1;
        o0.x = fmaf(a0.x, h0.x, c0 * b.x);
        o0.y = fmaf(a0.y, h0.y, c0 * b.y);
        o0.z = fmaf(a0.z, h0.z, c0 * b.z);
        o0.w = fmaf(a0.w, h0.w, c0 * b.w);
        o1.x = fmaf(a1.x, h1.x, c1 * b.x);
        o1.y = fmaf(a1.y, h1.y, c1 * b.y);
        o1.z = fmaf(a1.z, h1.z, c1 * b.z);
        o1.w = fmaf(a1.w, h1.w, c1 * b.w);
        __stcs(out4 + base + i0, o0);
        __stcs(out4 + base + i1, o1);
    }
}

extern "C" void kernel_launch(void* const* d_in, const int* in_sizes, int n_in,
                              void* d_out, int out_size) {
    const float* x    = (const float*)d_in[0];   // [256,5120]
    const float* W1   = (const float*)d_in[1];   // [5120,160]
    const float* W2   = (const float*)d_in[2];   // [160,5120]
    const float* bias = (const float*)d_in[3];   // [5120]
    const float* Bp   = (const float*)d_in[4];   // [5120,16]
    const float* abar = (const float*)d_in[5];   // [256,5120,16]
    const float* hst  = (const float*)d_in[6];   // [256,5120,16]
    float* out = (float*)d_out;

    stage1_kernel<<<dim3(U_DIM / S1_UT, S1_SPLITS), 256>>>(x, W1, Bp);
    reduce_kernel<<<RED_F4 / 256, 256>>>();
    fused_kernel<<<dim3(U_DIM / FU_UT, D_DIM / FU_DT), 256>>>(
        W2, bias, x, (const float4*)abar, (const float4*)hst, (float4*)out);
}